// round 17
// baseline (speedup 1.0000x reference)
#include <cuda_runtime.h>
#include <cuda_bf16.h>
#include <cuda_fp16.h>
#include <math.h>
#include <stdint.h>

#define NN 50000
#define EE 800000

// ---------------- device scratch ----------------
__device__ float g_bufA[NN * 256];
__device__ float g_z[NN * 64];
__device__ __nv_bfloat16 g_ahi[NN * 256];
__device__ __nv_bfloat16 g_alo[NN * 256];
__device__ __nv_bfloat16 g_bhi[NN * 256];
__device__ __nv_bfloat16 g_blo[NN * 256];
__device__ __nv_bfloat16 g_wthi[208896];
__device__ __nv_bfloat16 g_wtlo[208896];
__device__ float g_bfuse[64];
__device__ int   g_deg[NN];
__device__ float g_dinv[NN];
__device__ float g_dinv2[NN];
__device__ int   g_rowstart[NN + 1];
__device__ int   g_cursor[NN];
__device__ int   g_bsum[256];
__device__ int   g_boff[256];
__device__ int   g_src32[EE];
__device__ int   g_dst32[EE];
__device__ int   g_csr_src[EE];
__device__ float g_csr_norm[EE];
__device__ float g_t1[NN];
__device__ float g_t2[NN];
__device__ int   g_flag[1];

// ---------------- prep kernels ----------------
__global__ void detect_kernel(const long long* ei) {
    if (blockIdx.x == 0 && threadIdx.x == 0) {
        int ok = 1;
        for (int i = 0; i < 128; i++) {
            long long v = ei[i];
            if (v < 0 || v >= NN) { ok = 0; break; }
        }
        g_flag[0] = ok;
    }
}

__global__ void convert_hist_kernel(const void* ei, int E) {
    int i = blockIdx.x * blockDim.x + threadIdx.x;
    if (i >= E) return;
    int s, d;
    if (g_flag[0]) {
        const long long* p = (const long long*)ei;
        s = (int)p[i]; d = (int)p[i + E];
    } else {
        const int* p = (const int*)ei;
        s = p[i]; d = p[i + E];
    }
    g_src32[i] = s;
    g_dst32[i] = d;
    atomicAdd(&g_deg[d], 1);
}

__global__ __launch_bounds__(256) void scan_p1_kernel(int n) {
    __shared__ int wsum[8];
    int tid = threadIdx.x;
    int i = blockIdx.x * 256 + tid;
    int v = (i < n) ? g_deg[i] : 0;
    if (i < n) {
        float di = rsqrtf((float)(v + 1));
        g_dinv[i]  = di;
        g_dinv2[i] = di * di;
    }
    int x = v;
    #pragma unroll
    for (int o = 1; o < 32; o <<= 1) {
        int t = __shfl_up_sync(0xffffffffu, x, o);
        if ((tid & 31) >= o) x += t;
    }
    if ((tid & 31) == 31) wsum[tid >> 5] = x;
    __syncthreads();
    if (tid < 8) {
        int w = wsum[tid];
        #pragma unroll
        for (int o = 1; o < 8; o <<= 1) {
            int t = __shfl_up_sync(0xffu, w, o);
            if (tid >= o) w += t;
        }
        wsum[tid] = w;
    }
    __syncthreads();
    int incl = x + ((tid >= 32) ? wsum[(tid >> 5) - 1] : 0);
    if (i < n) g_rowstart[i] = incl - v;
    if (tid == 255) g_bsum[blockIdx.x] = incl;
}

__global__ __launch_bounds__(256) void scan_p2_kernel(int nb, int n) {
    __shared__ int wsum[8];
    int tid = threadIdx.x;
    int v = (tid < nb) ? g_bsum[tid] : 0;
    int x = v;
    #pragma unroll
    for (int o = 1; o < 32; o <<= 1) {
        int t = __shfl_up_sync(0xffffffffu, x, o);
        if ((tid & 31) >= o) x += t;
    }
    if ((tid & 31) == 31) wsum[tid >> 5] = x;
    __syncthreads();
    if (tid < 8) {
        int w = wsum[tid];
        #pragma unroll
        for (int o = 1; o < 8; o <<= 1) {
            int t = __shfl_up_sync(0xffu, w, o);
            if (tid >= o) w += t;
        }
        wsum[tid] = w;
    }
    __syncthreads();
    int incl = x + ((tid >= 32) ? wsum[(tid >> 5) - 1] : 0);
    if (tid < nb) g_boff[tid] = incl - v;
    if (tid == 255) g_rowstart[n] = incl;
}

__global__ __launch_bounds__(256) void scan_p3_kernel(int n) {
    int i = blockIdx.x * 256 + threadIdx.x;
    if (i >= n) return;
    int r = g_rowstart[i] + g_boff[blockIdx.x];
    g_rowstart[i] = r;
    g_cursor[i]   = r;
}

__global__ void scatter_kernel(int E) {
    int i = blockIdx.x * blockDim.x + threadIdx.x;
    if (i >= E) return;
    int s = g_src32[i], d = g_dst32[i];
    int pos = atomicAdd(&g_cursor[d], 1);
    g_csr_src[pos]  = s;
    g_csr_norm[pos] = g_dinv[s] * g_dinv[d];
}

// ---------------- split helpers ----------------
__device__ __forceinline__ void bf16_split(float v, __nv_bfloat16& h, __nv_bfloat16& l) {
    h = __float2bfloat16(v);
    l = __float2bfloat16(v - __bfloat162float(h));
}
__device__ __forceinline__ void f16_split(float v, __half& h, __half& l) {
    h = __float2half_rn(v);
    l = __float2half_rn(v - __half2float(h));
}
__device__ __forceinline__ void split2pack(float a, float b, uint32_t& h, uint32_t& l) {
    __nv_bfloat16 ha, la, hb, lb;
    bf16_split(a, ha, la);
    bf16_split(b, hb, lb);
    __nv_bfloat162 H(ha, hb), L(la, lb);
    h = *(uint32_t*)&H;
    l = *(uint32_t*)&L;
}

// weight transposes+splits for ew1, dw1, dw2 (bf16 GEMMs)
__global__ void wsplit_all_kernel(const float* __restrict__ ew1,
                                  const float* __restrict__ dw1,
                                  const float* __restrict__ dw2,
                                  __nv_bfloat16* __restrict__ hi,
                                  __nv_bfloat16* __restrict__ lo) {
    int i = blockIdx.x * blockDim.x + threadIdx.x;
    if (i >= 65536) return;
    const float* W; int K, Nc, j, out;
    if (i < 16384)       { W = ew1; K = 128; Nc = 128; j = i;         out = 0 + j; }
    else if (i < 32768)  { W = dw1; K = 64;  Nc = 256; j = i - 16384; out = 28672 + j; }
    else                 { W = dw2; K = 256; Nc = 128; j = i - 32768; out = 45056 + j; }
    int n = j / K, k = j - n * K;
    __nv_bfloat16 h, l;
    bf16_split(W[(size_t)k * Nc + n], h, l);
    hi[out] = h; lo[out] = l;
}

// fuse W' = ew2 @ efw -> transposed [64][128] bf16 hi/lo at O_EW2;
// b' = eb2 @ efw + efb -> g_bfuse
__global__ void wfuse_kernel(const float* __restrict__ ew2,
                             const float* __restrict__ efw,
                             const float* __restrict__ eb2,
                             const float* __restrict__ efb,
                             __nv_bfloat16* __restrict__ hi,
                             __nv_bfloat16* __restrict__ lo) {
    int i = blockIdx.x * blockDim.x + threadIdx.x;
    if (i < 8192) {
        int n = i & 63, k = i >> 6;        // W'[k][n], stored Wt[n*128+k]
        float acc = 0.f;
        #pragma unroll 8
        for (int j = 0; j < 64; j++)
            acc += ew2[k * 64 + j] * efw[j * 64 + n];
        __nv_bfloat16 h, l;
        bf16_split(acc, h, l);
        hi[16384 + n * 128 + k] = h;       // O_EW2 = 16384
        lo[16384 + n * 128 + k] = l;
    } else if (i < 8256) {
        int n = i - 8192;
        float acc = efb[n];
        #pragma unroll 8
        for (int j = 0; j < 64; j++)
            acc += eb2[j] * efw[j * 64 + n];
        g_bfuse[n] = acc;
    }
}

__global__ void wsplit_dfw_f16_kernel(const float* __restrict__ W,
                                      __half* __restrict__ out) {
    int i = blockIdx.x * blockDim.x + threadIdx.x;   // [Nc=1024][K=128]
    if (i >= 1024 * 128) return;
    int n = i >> 7, k = i & 127;
    out[i] = __float2half_rn(W[(size_t)k * 1024 + n]);
}

// ---------------- mma.sync helpers ----------------
__device__ __forceinline__ void mma_bf16(float* c, const uint32_t* a, const uint32_t* b) {
    asm volatile(
        "mma.sync.aligned.m16n8k16.row.col.f32.bf16.bf16.f32 "
        "{%0,%1,%2,%3}, {%4,%5,%6,%7}, {%8,%9}, {%0,%1,%2,%3};"
        : "+f"(c[0]), "+f"(c[1]), "+f"(c[2]), "+f"(c[3])
        : "r"(a[0]), "r"(a[1]), "r"(a[2]), "r"(a[3]), "r"(b[0]), "r"(b[1]));
}
__device__ __forceinline__ void mma_f16(float* c, const uint32_t* a, const uint32_t* b) {
    asm volatile(
        "mma.sync.aligned.m16n8k16.row.col.f32.f16.f16.f32 "
        "{%0,%1,%2,%3}, {%4,%5,%6,%7}, {%8,%9}, {%0,%1,%2,%3};"
        : "+f"(c[0]), "+f"(c[1]), "+f"(c[2]), "+f"(c[3])
        : "r"(a[0]), "r"(a[1]), "r"(a[2]), "r"(a[3]), "r"(b[0]), "r"(b[1]));
}
__device__ __forceinline__ void ldsm_x4(uint32_t& r0, uint32_t& r1,
                                        uint32_t& r2, uint32_t& r3, uint32_t addr) {
    asm volatile("ldmatrix.sync.aligned.m8n8.x4.shared.b16 {%0,%1,%2,%3}, [%4];"
        : "=r"(r0), "=r"(r1), "=r"(r2), "=r"(r3) : "r"(addr));
}
__device__ __forceinline__ uint32_t smem_u32(const void* p) {
    uint32_t a;
    asm("{ .reg .u64 t; cvta.to.shared.u64 t, %1; cvt.u32.u64 %0, t; }"
        : "=r"(a) : "l"(p));
    return a;
}

#define PITCH 72

// ---------------- bf16 3-product GEMM ----------------
template<int BIAS, int RELU, int SPLIT, int AF32, int CF16>
__global__ __launch_bounds__(256) void mma_gemm_kernel(
    const void* A1, const void* A2,
    const __nv_bfloat16* __restrict__ Whi, const __nv_bfloat16* __restrict__ Wlo,
    const float* __restrict__ bias,
    float* __restrict__ Cf, __half* __restrict__ Cf16,
    __nv_bfloat16* __restrict__ Chi, __nv_bfloat16* __restrict__ Clo,
    int M, int Nc, int K, int rowOff)
{
    __shared__ __nv_bfloat16 sAhi[128 * PITCH];
    __shared__ __nv_bfloat16 sAlo[128 * PITCH];
    __shared__ __nv_bfloat16 sBhi[64 * PITCH];
    __shared__ __nv_bfloat16 sBlo[64 * PITCH];

    int tid  = threadIdx.x;
    int wid  = tid >> 5, lane = tid & 31;
    int wm   = wid & 3;
    int wn   = wid >> 2;
    int g    = lane >> 2;
    int t    = lane & 3;
    int bm   = rowOff + blockIdx.y * 128, bn = blockIdx.x * 64;

    float acc[2][4][4];
    #pragma unroll
    for (int i = 0; i < 2; i++)
        #pragma unroll
        for (int j = 0; j < 4; j++)
            #pragma unroll
            for (int r = 0; r < 4; r++) acc[i][j][r] = 0.f;

    int aRow0 = wm * 32 + (lane & 15);
    int aColB = (lane & 16) ? 16 : 0;
    uint32_t uAhi = smem_u32(sAhi), uAlo = smem_u32(sAlo);
    uint32_t aHi0 = uAhi + (uint32_t)(aRow0 * PITCH * 2 + aColB);
    uint32_t aLo0 = uAlo + (uint32_t)(aRow0 * PITCH * 2 + aColB);
    int bRow0 = wn * 32 + (lane & 7) + ((lane & 16) ? 8 : 0);
    int bColB = (lane & 8) ? 16 : 0;
    uint32_t uBhi = smem_u32(sBhi), uBlo = smem_u32(sBlo);
    uint32_t bHi0 = uBhi + (uint32_t)(bRow0 * PITCH * 2 + bColB);
    uint32_t bLo0 = uBlo + (uint32_t)(bRow0 * PITCH * 2 + bColB);
    const uint32_t AROWS16 = 16 * PITCH * 2;

    int arow = tid >> 1, ahalf = tid & 1;
    int btt = tid & 127;
    int brow = btt >> 1, bhalf = btt & 1;

    for (int kc = 0; kc < K; kc += 64) {
        __syncthreads();
        {
            __nv_bfloat16* dH = sAhi + arow * PITCH + ahalf * 32;
            __nv_bfloat16* dL = sAlo + arow * PITCH + ahalf * 32;
            int grow = bm + arow;
            if (grow < M) {
                if (AF32) {
                    const float4* xr = (const float4*)((const float*)A1 +
                        (size_t)grow * K + kc + ahalf * 32);
                    #pragma unroll
                    for (int c = 0; c < 4; c++) {
                        float4 f0 = xr[2 * c];
                        float4 f1 = xr[2 * c + 1];
                        uint32_t h0, l0, h1, l1, h2, l2, h3, l3;
                        split2pack(f0.x, f0.y, h0, l0);
                        split2pack(f0.z, f0.w, h1, l1);
                        split2pack(f1.x, f1.y, h2, l2);
                        split2pack(f1.z, f1.w, h3, l3);
                        ((uint4*)(dH + 8 * c))[0] = make_uint4(h0, h1, h2, h3);
                        ((uint4*)(dL + 8 * c))[0] = make_uint4(l0, l1, l2, l3);
                    }
                } else {
                    const uint4* sh = (const uint4*)((const __nv_bfloat16*)A1 +
                        (size_t)grow * K + kc + ahalf * 32);
                    const uint4* sl = (const uint4*)((const __nv_bfloat16*)A2 +
                        (size_t)grow * K + kc + ahalf * 32);
                    #pragma unroll
                    for (int c = 0; c < 4; c++) {
                        ((uint4*)dH)[c] = sh[c];
                        ((uint4*)dL)[c] = sl[c];
                    }
                }
            } else {
                uint4 z = make_uint4(0, 0, 0, 0);
                #pragma unroll
                for (int c = 0; c < 4; c++) { ((uint4*)dH)[c] = z; ((uint4*)dL)[c] = z; }
            }
        }
        {
            const __nv_bfloat16* W = (tid < 128) ? Whi : Wlo;
            __nv_bfloat16* dst = ((tid < 128) ? sBhi : sBlo) + brow * PITCH + bhalf * 32;
            const uint4* src = (const uint4*)(W + (size_t)(bn + brow) * K + kc + bhalf * 32);
            #pragma unroll
            for (int c = 0; c < 4; c++) ((uint4*)dst)[c] = src[c];
        }
        __syncthreads();

        #pragma unroll
        for (int ks = 0; ks < 4; ks++) {
            uint32_t ofs = ks * 32;
            uint32_t ah0[4], ah1[4], al0[4], al1[4];
            ldsm_x4(ah0[0], ah0[1], ah0[2], ah0[3], aHi0 + ofs);
            ldsm_x4(ah1[0], ah1[1], ah1[2], ah1[3], aHi0 + AROWS16 + ofs);
            ldsm_x4(al0[0], al0[1], al0[2], al0[3], aLo0 + ofs);
            ldsm_x4(al1[0], al1[1], al1[2], al1[3], aLo0 + AROWS16 + ofs);
            uint32_t bh[4][2], bl[4][2];
            ldsm_x4(bh[0][0], bh[0][1], bh[1][0], bh[1][1], bHi0 + ofs);
            ldsm_x4(bh[2][0], bh[2][1], bh[3][0], bh[3][1], bHi0 + AROWS16 + ofs);
            ldsm_x4(bl[0][0], bl[0][1], bl[1][0], bl[1][1], bLo0 + ofs);
            ldsm_x4(bl[2][0], bl[2][1], bl[3][0], bl[3][1], bLo0 + AROWS16 + ofs);
            #pragma unroll
            for (int na = 0; na < 4; na++) {
                mma_bf16(acc[0][na], ah0, bh[na]);
                mma_bf16(acc[0][na], ah0, bl[na]);
                mma_bf16(acc[0][na], al0, bh[na]);
                mma_bf16(acc[1][na], ah1, bh[na]);
                mma_bf16(acc[1][na], ah1, bl[na]);
                mma_bf16(acc[1][na], al1, bh[na]);
            }
        }
    }

    #pragma unroll
    for (int ma = 0; ma < 2; ma++) {
        #pragma unroll
        for (int half = 0; half < 2; half++) {
            int row = bm + wm * 32 + ma * 16 + g + half * 8;
            if (row >= M) continue;
            #pragma unroll
            for (int na = 0; na < 4; na++) {
                int col = bn + wn * 32 + na * 8 + 2 * t;
                float v0 = acc[ma][na][half * 2 + 0];
                float v1 = acc[ma][na][half * 2 + 1];
                if (BIAS) { v0 += __ldg(bias + col); v1 += __ldg(bias + col + 1); }
                if (RELU) { v0 = fmaxf(v0, 0.f); v1 = fmaxf(v1, 0.f); }
                if (SPLIT) {
                    __nv_bfloat16 h0, l0, h1, l1;
                    bf16_split(v0, h0, l0);
                    bf16_split(v1, h1, l1);
                    *(__nv_bfloat162*)(Chi + (size_t)row * Nc + col) = __nv_bfloat162(h0, h1);
                    *(__nv_bfloat162*)(Clo + (size_t)row * Nc + col) = __nv_bfloat162(l0, l1);
                } else if (CF16) {
                    *(__half2*)(Cf16 + (size_t)row * Nc + col) =
                        __half2(__float2half_rn(v0), __float2half_rn(v1));
                } else {
                    *(float2*)(Cf + (size_t)row * Nc + col) = make_float2(v0, v1);
                }
            }
        }
    }
}

// ---------------- fp16 2-product GEMM (final output layer) ----------------
__global__ __launch_bounds__(256) void mma_gemm_f16_kernel(
    const __half* __restrict__ Ahi, const __half* __restrict__ Alo,
    const __half* __restrict__ W,
    const float* __restrict__ bias,
    float* __restrict__ Cf,
    int M, int Nc, int K, int rowOff)
{
    __shared__ __half sAhi[128 * PITCH];
    __shared__ __half sAlo[128 * PITCH];
    __shared__ __half sB[64 * PITCH];

    int tid  = threadIdx.x;
    int wid  = tid >> 5, lane = tid & 31;
    int wm   = wid & 3;
    int wn   = wid >> 2;
    int g    = lane >> 2;
    int t    = lane & 3;
    int bm   = rowOff + blockIdx.y * 128, bn = blockIdx.x * 64;

    float acc[2][4][4];
    #pragma unroll
    for (int i = 0; i < 2; i++)
        #pragma unroll
        for (int j = 0; j < 4; j++)
            #pragma unroll
            for (int r = 0; r < 4; r++) acc[i][j][r] = 0.f;

    int aRow0 = wm * 32 + (lane & 15);
    int aColB = (lane & 16) ? 16 : 0;
    uint32_t uAhi = smem_u32(sAhi), uAlo = smem_u32(sAlo);
    uint32_t aHi0 = uAhi + (uint32_t)(aRow0 * PITCH * 2 + aColB);
    uint32_t aLo0 = uAlo + (uint32_t)(aRow0 * PITCH * 2 + aColB);
    int bRow0 = wn * 32 + (lane & 7) + ((lane & 16) ? 8 : 0);
    int bColB = (lane & 8) ? 16 : 0;
    uint32_t uB = smem_u32(sB);
    uint32_t bB0 = uB + (uint32_t)(bRow0 * PITCH * 2 + bColB);
    const uint32_t AROWS16 = 16 * PITCH * 2;

    int arow = tid >> 1, ahalf = tid & 1;
    int btt = tid & 127;
    int brow = btt >> 1, bhalf = btt & 1;

    for (int kc = 0; kc < K; kc += 64) {
        __syncthreads();
        {
            __half* dH = sAhi + arow * PITCH + ahalf * 32;
            __half* dL = sAlo + arow * PITCH + ahalf * 32;
            int grow = bm + arow;
            if (grow < M) {
                const uint4* sh = (const uint4*)(Ahi + (size_t)grow * K + kc + ahalf * 32);
                const uint4* sl = (const uint4*)(Alo + (size_t)grow * K + kc + ahalf * 32);
                #pragma unroll
                for (int c = 0; c < 4; c++) {
                    ((uint4*)dH)[c] = sh[c];
                    ((uint4*)dL)[c] = sl[c];
                }
            } else {
                uint4 z = make_uint4(0, 0, 0, 0);
                #pragma unroll
                for (int c = 0; c < 4; c++) { ((uint4*)dH)[c] = z; ((uint4*)dL)[c] = z; }
            }
        }
        if (tid < 128) {
            __half* dst = sB + brow * PITCH + bhalf * 32;
            const uint4* src = (const uint4*)(W + (size_t)(bn + brow) * K + kc + bhalf * 32);
            #pragma unroll
            for (int c = 0; c < 4; c++) ((uint4*)dst)[c] = src[c];
        }
        __syncthreads();

        #pragma unroll
        for (int ks = 0; ks < 4; ks++) {
            uint32_t ofs = ks * 32;
            uint32_t ah0[4], ah1[4], al0[4], al1[4];
            ldsm_x4(ah0[0], ah0[1], ah0[2], ah0[3], aHi0 + ofs);
            ldsm_x4(ah1[0], ah1[1], ah1[2], ah1[3], aHi0 + AROWS16 + ofs);
            ldsm_x4(al0[0], al0[1], al0[2], al0[3], aLo0 + ofs);
            ldsm_x4(al1[0], al1[1], al1[2], al1[3], aLo0 + AROWS16 + ofs);
            uint32_t b[4][2];
            ldsm_x4(b[0][0], b[0][1], b[1][0], b[1][1], bB0 + ofs);
            ldsm_x4(b[2][0], b[2][1], b[3][0], b[3][1], bB0 + AROWS16 + ofs);
            #pragma unroll
            for (int na = 0; na < 4; na++) {
                mma_f16(acc[0][na], ah0, b[na]);
                mma_f16(acc[0][na], al0, b[na]);
                mma_f16(acc[1][na], ah1, b[na]);
                mma_f16(acc[1][na], al1, b[na]);
            }
        }
    }

    #pragma unroll
    for (int ma = 0; ma < 2; ma++) {
        #pragma unroll
        for (int half = 0; half < 2; half++) {
            int row = bm + wm * 32 + ma * 16 + g + half * 8;
            if (row >= M) continue;
            #pragma unroll
            for (int na = 0; na < 4; na++) {
                int col = bn + wn * 32 + na * 8 + 2 * t;
                float v0 = acc[ma][na][half * 2 + 0] + __ldg(bias + col);
                float v1 = acc[ma][na][half * 2 + 1] + __ldg(bias + col + 1);
                asm volatile("st.global.cs.v2.f32 [%0], {%1, %2};"
                    :: "l"(Cf + (size_t)row * Nc + col), "f"(v0), "f"(v1));
            }
        }
    }
}

// ---------------- fp16-gather aggregation ----------------
// OMODE 0: bf16 hi/lo out; 1: fp16 hi/lo out; 2: fp32 out to o1 + fp16 copy to o2
template<int F, int RELU, int BIAS, int OMODE>
__global__ __launch_bounds__(256) void agg_h_kernel(
    const __half* __restrict__ h, const float* __restrict__ bias,
    void* o1_, void* o2_, int n0, int n1)
{
    int gw = n0 + ((blockIdx.x * blockDim.x + threadIdx.x) >> 5);
    int lane = threadIdx.x & 31;
    if (gw >= n1) return;
    constexpr int V = F / 32;
    float acc[V];
    #pragma unroll
    for (int i = 0; i < V; i++) acc[i] = 0.f;
    int e0 = g_rowstart[gw], e1 = g_rowstart[gw + 1];
    const __half* basep = h + lane * V;
    #pragma unroll 2
    for (int e = e0; e < e1; e++) {
        int s = __ldg(&g_csr_src[e]);
        float w = __ldg(&g_csr_norm[e]);
        if (V == 2) {
            uint32_t u = *(const uint32_t*)(basep + (size_t)s * F);
            float2 f = __half22float2(*(__half2*)&u);
            acc[0] += f.x * w; acc[1] += f.y * w;
        } else {
            uint2 u = *(const uint2*)(basep + (size_t)s * F);
            float2 f0 = __half22float2(*(__half2*)&u.x);
            float2 f1 = __half22float2(*(__half2*)&u.y);
            acc[0] += f0.x * w; acc[1] += f0.y * w;
            acc[2] += f1.x * w; acc[3] += f1.y * w;
        }
    }
    float sw = g_dinv2[gw];
    float v[V];
    if (V == 2) {
        uint32_t su = *(const uint32_t*)(basep + (size_t)gw * F);
        float2 s = __half22float2(*(__half2*)&su);
        v[0] = acc[0] + s.x * sw; v[1] = acc[1] + s.y * sw;
    } else {
        uint2 su = *(const uint2*)(basep + (size_t)gw * F);
        float2 s0 = __half22float2(*(__half2*)&su.x);
        float2 s1 = __half22float2(*(__half2*)&su.y);
        v[0] = acc[0] + s0.x * sw; v[1] = acc[1] + s0.y * sw;
        v[2] = acc[2] + s1.x * sw; v[3] = acc[3] + s1.y * sw;
    }
    #pragma unroll
    for (int i = 0; i < V; i++) {
        if (BIAS) v[i] += bias[lane * V + i];
        if (RELU) v[i] = fmaxf(v[i], 0.f);
    }
    size_t base = (size_t)gw * F + lane * V;
    if (OMODE == 0) {
        __nv_bfloat16* oh = (__nv_bfloat16*)o1_ + base;
        __nv_bfloat16* ol = (__nv_bfloat16*)o2_ + base;
        #pragma unroll
        for (int i = 0; i < V; i += 2) {
            __nv_bfloat16 h0, l0, h1, l1;
            bf16_split(v[i], h0, l0);
            bf16_split(v[i + 1], h1, l1);
            *(__nv_bfloat162*)(oh + i) = __nv_bfloat162(h0, h1);
            *(__nv_bfloat162*)(ol + i) = __nv_bfloat162(l0, l1);
        }
    } else if (OMODE == 1) {
        __half* oh = (__half*)o1_ + base;
        __half* ol = (__half*)o2_ + base;
        #pragma unroll
        for (int i = 0; i < V; i += 2) {
            __half h0, l0, h1, l1;
            f16_split(v[i], h0, l0);
            f16_split(v[i + 1], h1, l1);
            *(__half2*)(oh + i) = __half2(h0, h1);
            *(__half2*)(ol + i) = __half2(l0, l1);
        }
    } else {
        float* of = (float*)o1_ + base;
        __half* oh = (__half*)o2_ + base;
        #pragma unroll
        for (int i = 0; i < V; i += 2) {
            *(float2*)(of + i) = make_float2(v[i], v[i + 1]);
            *(__half2*)(oh + i) = __half2(__float2half_rn(v[i]), __float2half_rn(v[i + 1]));
        }
    }
}

// ---------------- link predictor ----------------
__global__ void lp_node_kernel(const float* __restrict__ z,
                               const float* __restrict__ lw, int N)
{
    int v = blockIdx.x * blockDim.x + threadIdx.x;
    if (v >= N) return;
    const float4* zr = (const float4*)(z + (size_t)v * 64);
    float a = 0.f, b = 0.f;
    #pragma unroll
    for (int i = 0; i < 16; i++) {
        float4 zz = zr[i];
        float4 w1 = __ldg(&((const float4*)lw)[i]);
        float4 w2 = __ldg(&((const float4*)lw)[16 + i]);
        a += zz.x * w1.x + zz.y * w1.y + zz.z * w1.z + zz.w * w1.w;
        b += zz.x * w2.x + zz.y * w2.y + zz.z * w2.z + zz.w * w2.w;
    }
    g_t1[v] = a;
    g_t2[v] = b;
}

__global__ void lp_edge_kernel(const float* __restrict__ lb,
                               float* __restrict__ out, int E)
{
    int e = blockIdx.x * blockDim.x + threadIdx.x;
    if (e >= E) return;
    float p = g_t1[g_src32[e]] + g_t2[g_dst32[e]] + lb[0];
    float v = 1.f / (1.f + expf(-p));
    asm volatile("st.global.cs.f32 [%0], %1;" :: "l"(out + e), "f"(v));
}

// ---------------- host launcher ----------------
extern "C" void kernel_launch(void* const* d_in, const int* in_sizes, int n_in,
                              void* d_out, int out_size)
{
    const float* x   = (const float*)d_in[0];
    const void*  ei  = d_in[1];
    const float* ew1 = (const float*)d_in[2];
    const float* eb1 = (const float*)d_in[3];
    const float* ew2 = (const float*)d_in[4];
    const float* eb2 = (const float*)d_in[5];
    const float* efw = (const float*)d_in[6];
    const float* efb = (const float*)d_in[7];
    const float* dw1 = (const float*)d_in[8];
    const float* db1 = (const float*)d_in[9];
    const float* dw2 = (const float*)d_in[10];
    const float* db2 = (const float*)d_in[11];
    const float* dfw = (const float*)d_in[12];
    const float* dfb = (const float*)d_in[13];
    const float* lw  = (const float*)d_in[14];
    const float* lb  = (const float*)d_in[15];

    int N = in_sizes[0] / 128;
    int E = in_sizes[1] / 2;
    if (N > NN) N = NN;
    if (E > EE) E = EE;

    float *bufA, *zbuf, *bfusep;
    __nv_bfloat16 *ahi, *alo, *bhi, *blo, *wthi, *wtlo;
    int* degp;
    cudaGetSymbolAddress((void**)&bufA, g_bufA);
    cudaGetSymbolAddress((void**)&zbuf, g_z);
    cudaGetSymbolAddress((void**)&ahi, g_ahi);
    cudaGetSymbolAddress((void**)&alo, g_alo);
    cudaGetSymbolAddress((void**)&bhi, g_bhi);
    cudaGetSymbolAddress((void**)&blo, g_blo);
    cudaGetSymbolAddress((void**)&wthi, g_wthi);
    cudaGetSymbolAddress((void**)&wtlo, g_wtlo);
    cudaGetSymbolAddress((void**)&degp, g_deg);
    cudaGetSymbolAddress((void**)&bfusep, g_bfuse);

    const int O_EW1 = 0;
    const int O_EW2 = O_EW1 + 128 * 128;   // fused ew2@efw (64x128)
    const int O_EFW = O_EW2 + 64 * 128;
    const int O_DW1 = O_EFW + 64 * 64;
    const int O_DW2 = O_DW1 + 256 * 64;
    const int O_DFW = O_DW2 + 128 * 256;   // fp16 region (reinterpreted)

    float* xhat  = (float*)d_out;
    float* eprob = (float*)d_out + (size_t)N * 1024;

    int nb  = (N + 255) / 256;
    int ebk = (E + 255) / 256;
    int rT  = (N + 127) / 128;

    int t0 = (rT + 1) / 2;
    int t1 = rT - t0;
    int NC0 = t0 * 128;
    int aggB0 = (NC0 + 7) / 8;
    int aggB1 = (N - NC0 + 7) / 8;
    int aggB  = (N + 7) / 8;

    static cudaStream_t sPrep = nullptr, sLp = nullptr, sAux = nullptr;
    static cudaEvent_t evRoot, evPrep, evZ, evLp, evG1, evA1, evA3, evD2, evA4;
    if (!sPrep) {
        cudaStreamCreateWithFlags(&sPrep, cudaStreamNonBlocking);
        cudaStreamCreateWithFlags(&sLp, cudaStreamNonBlocking);
        cudaStreamCreateWithFlags(&sAux, cudaStreamNonBlocking);
        cudaEventCreateWithFlags(&evRoot, cudaEventDisableTiming);
        cudaEventCreateWithFlags(&evPrep, cudaEventDisableTiming);
        cudaEventCreateWithFlags(&evZ, cudaEventDisableTiming);
        cudaEventCreateWithFlags(&evLp, cudaEventDisableTiming);
        cudaEventCreateWithFlags(&evG1, cudaEventDisableTiming);
        cudaEventCreateWithFlags(&evA1, cudaEventDisableTiming);
        cudaEventCreateWithFlags(&evA3, cudaEventDisableTiming);
        cudaEventCreateWithFlags(&evD2, cudaEventDisableTiming);
        cudaEventCreateWithFlags(&evA4, cudaEventDisableTiming);
    }

    cudaEventRecord(evRoot, 0);
    cudaStreamWaitEvent(sPrep, evRoot, 0);

    // ---- side stream: edge prep ----
    detect_kernel<<<1, 32, 0, sPrep>>>((const long long*)ei);
    cudaMemsetAsync(degp, 0, (size_t)N * sizeof(int), sPrep);
    convert_hist_kernel<<<ebk, 256, 0, sPrep>>>(ei, E);
    scan_p1_kernel<<<nb, 256, 0, sPrep>>>(N);
    scan_p2_kernel<<<1, 256, 0, sPrep>>>(nb, N);
    scan_p3_kernel<<<nb, 256, 0, sPrep>>>(N);
    scatter_kernel<<<ebk, 256, 0, sPrep>>>(E);
    cudaEventRecord(evPrep, sPrep);

    __half* h1buf = (__half*)zbuf;                  // gemm1 fp16 output [N,128]
    __half* yebuf = (__half*)bufA;                  // fused encoder GEMM out [N,64]
    __half* zh    = (__half*)bufA + (size_t)NN * 64; // fp16 z copy [N,64]
    __half* h4buf = (__half*)bufA;                  // dw2 out fp16 [N,128] (after zh consumed)

    // ---- main stream: weight prep + GEMM1 ----
    wsplit_all_kernel<<<(65536 + 255) / 256, 256>>>(ew1, dw1, dw2, wthi, wtlo);
    wfuse_kernel<<<(8256 + 255) / 256, 256>>>(ew2, efw, eb2, efb, wthi, wtlo);
    wsplit_dfw_f16_kernel<<<(1024 * 128 + 255) / 256, 256>>>(dfw, (__half*)(wthi + O_DFW));
    mma_gemm_kernel<0,0,0,1,1><<<dim3(2, rT), 256>>>(
        x, nullptr, wthi + O_EW1, wtlo + O_EW1, nullptr,
        nullptr, h1buf, nullptr, nullptr, N, 128, 128, 0);

    cudaStreamWaitEvent(0, evPrep, 0);
    cudaEventRecord(evG1, 0);

    // agg1 chunked (fp16 gather F=128, relu+bias, bf16 out)
    agg_h_kernel<128,1,1,0><<<aggB0, 256>>>(h1buf, eb1, ahi, alo, 0, NC0);
    cudaStreamWaitEvent(sAux, evG1, 0);
    agg_h_kernel<128,1,1,0><<<aggB1, 256, 0, sAux>>>(h1buf, eb1, ahi, alo, NC0, N);
    cudaEventRecord(evA1, sAux);

    // fused encoder GEMM (128 -> 64, W' = ew2@efw), fp16 out, chunked
    mma_gemm_kernel<0,0,0,0,1><<<dim3(1, t0), 256>>>(
        ahi, alo, wthi + O_EW2, wtlo + O_EW2, nullptr,
        nullptr, yebuf, nullptr, nullptr, N, 64, 128, 0);
    cudaStreamWaitEvent(0, evA1, 0);
    mma_gemm_kernel<0,0,0,0,1><<<dim3(1, t1), 256>>>(
        ahi, alo, wthi + O_EW2, wtlo + O_EW2, nullptr,
        nullptr, yebuf, nullptr, nullptr, N, 64, 128, NC0);

    // agg2: fp16 gather F=64, bias=b', out fp32 z + fp16 zh
    agg_h_kernel<64,0,1,2><<<aggB, 256>>>(yebuf, bfusep, zbuf, zh, 0, N);
    cudaEventRecord(evZ, 0);

    // link predictor fork
    cudaStreamWaitEvent(sLp, evZ, 0);
    lp_node_kernel<<<nb, 256, 0, sLp>>>(zbuf, lw, N);
    lp_edge_kernel<<<ebk, 256, 0, sLp>>>(lb, eprob, E);
    cudaEventRecord(evLp, sLp);

    // agg3 chunked (fp16 gather F=64 of zh, bf16 out), overlapped with dw1(c0)
    agg_h_kernel<64,0,0,0><<<aggB0, 256>>>(zh, nullptr, ahi, alo, 0, NC0);
    cudaStreamWaitEvent(sAux, evZ, 0);
    agg_h_kernel<64,0,0,0><<<aggB1, 256, 0, sAux>>>(zh, nullptr, ahi, alo, NC0, N);
    cudaEventRecord(evA3, sAux);

    mma_gemm_kernel<1,1,1,0,0><<<dim3(4, t0), 256>>>(
        ahi, alo, wthi + O_DW1, wtlo + O_DW1, db1,
        nullptr, nullptr, bhi, blo, N, 256, 64, 0);
    cudaStreamWaitEvent(0, evA3, 0);
    mma_gemm_kernel<1,1,1,0,0><<<dim3(4, t1), 256>>>(
        ahi, alo, wthi + O_DW1, wtlo + O_DW1, db1,
        nullptr, nullptr, bhi, blo, N, 256, 64, NC0);

    mma_gemm_kernel<0,0,0,0,1><<<dim3(2, rT), 256>>>(
        bhi, blo, wthi + O_DW2, wtlo + O_DW2, nullptr,
        nullptr, h4buf, nullptr, nullptr, N, 128, 256, 0);
    cudaEventRecord(evD2, 0);

    // agg4 chunked (fp16 gather F=128, bias, fp16 split out)
    agg_h_kernel<128,0,1,1><<<aggB0, 256>>>(h4buf, db2, (__half*)ahi, (__half*)alo, 0, NC0);
    cudaStreamWaitEvent(sAux, evD2, 0);
    agg_h_kernel<128,0,1,1><<<aggB1, 256, 0, sAux>>>(h4buf, db2, (__half*)ahi, (__half*)alo, NC0, N);
    cudaEventRecord(evA4, sAux);

    mma_gemm_f16_kernel<<<dim3(16, t0), 256>>>(
        (__half*)ahi, (__half*)alo, (__half*)(wthi + O_DFW), dfb, xhat, N, 1024, 128, 0);
    cudaStreamWaitEvent(0, evA4, 0);
    mma_gemm_f16_kernel<<<dim3(16, t1), 256>>>(
        (__half*)ahi, (__half*)alo, (__half*)(wthi + O_DFW), dfb, xhat, N, 1024, 128, NC0);

    cudaStreamWaitEvent(0, evLp, 0);
}